// round 7
// baseline (speedup 1.0000x reference)
#include <cuda_runtime.h>
#include <cuda_fp16.h>
#include <stdint.h>

#define N_NODES 50000
#define E_EDGES 800000
#define D 128
#define SCAN_B 512
#define NBLK ((N_NODES + SCAN_B - 1) / SCAN_B)   // 98
#define GTILES ((N_NODES + 127) / 128)           // 391
#define GS 136                                    // smem f16 stride (bank-safe)

// ---------------------------------------------------------------------------
// Scratch (__device__ globals; zero-initialized at module load; no allocs).
// ---------------------------------------------------------------------------
__device__ __half g_Wh0[(size_t)N_NODES * D];
__device__ __half g_Wh1[(size_t)N_NODES * D];
__device__ int   g_cnt0[N_NODES];     // re-zeroed by fill_kernel each call
__device__ int   g_cnt1[N_NODES];
__device__ int   g_offs0[N_NODES];    // scan writes starts; fill bumps to ends
__device__ int   g_offs1[N_NODES];
__device__ int   g_srt0[E_EDGES];
__device__ int   g_srt1[E_EDGES];
__device__ int   g_bsum0[NBLK];
__device__ int   g_bsum1[NBLK];

// ---------------------------------------------------------------------------
// Host-side stream/event resources (created once; host-only resources).
// ---------------------------------------------------------------------------
struct SideStream {
    cudaStream_t s;
    cudaEvent_t  fork, join;
    SideStream() {
        cudaStreamCreateWithFlags(&s, cudaStreamNonBlocking);
        cudaEventCreateWithFlags(&fork, cudaEventDisableTiming);
        cudaEventCreateWithFlags(&join, cudaEventDisableTiming);
    }
};
static SideStream g_ss;

// ---------------------------------------------------------------------------
// Warp-level HMMA m16n8k16 (sm_80+ baseline PTX).
// ---------------------------------------------------------------------------
__device__ __forceinline__ void mma16816(float* d,
                                         uint32_t a0, uint32_t a1,
                                         uint32_t a2, uint32_t a3,
                                         uint32_t b0, uint32_t b1) {
    asm volatile(
        "mma.sync.aligned.m16n8k16.row.col.f32.f16.f16.f32 "
        "{%0,%1,%2,%3}, {%4,%5,%6,%7}, {%8,%9}, {%0,%1,%2,%3};"
        : "+f"(d[0]), "+f"(d[1]), "+f"(d[2]), "+f"(d[3])
        : "r"(a0), "r"(a1), "r"(a2), "r"(a3), "r"(b0), "r"(b1));
}

// ---------------------------------------------------------------------------
// HMMA GEMM: Wh = fp16(feat @ W + b), Markidis hi/lo split. Side stream.
// ---------------------------------------------------------------------------
__global__ __launch_bounds__(256, 1) void mma_gemm_kernel(
    const float* __restrict__ feat,
    const float* __restrict__ W0, const float* __restrict__ b0,
    const float* __restrict__ W1, const float* __restrict__ b1)
{
    extern __shared__ __align__(16) char smem[];
    __half* sAh = reinterpret_cast<__half*>(smem);
    __half* sAl = sAh + 128 * GS;
    __half* sBh = sAl + 128 * GS;
    __half* sBl = sBh + 128 * GS;

    const int rel = blockIdx.y;
    const float* __restrict__ W    = rel ? W1 : W0;
    const float* __restrict__ bias = rel ? b1 : b0;
    __half* __restrict__ Wh = rel ? g_Wh1 : g_Wh0;

    const int tid  = threadIdx.x;
    const int row0 = blockIdx.x * 128;

    for (int i = tid; i < D * D; i += 256) {
        const int k = i >> 7, n = i & 127;
        const float w = __ldg(W + i);
        const __half h = __float2half_rn(w);
        const __half l = __float2half_rn(w - __half2float(h));
        sBh[n * GS + k] = h;
        sBl[n * GS + k] = l;
    }
    for (int i = tid; i < 128 * D; i += 256) {
        const int r = i >> 7, k = i & 127;
        const int gr = row0 + r;
        const float a = (gr < N_NODES) ? __ldg(feat + (size_t)gr * D + k) : 0.f;
        const __half h = __float2half_rn(a);
        const __half l = __float2half_rn(a - __half2float(h));
        sAh[r * GS + k] = h;
        sAl[r * GS + k] = l;
    }
    __syncthreads();

    const int wid   = tid >> 5;
    const int lane  = tid & 31;
    const int group = lane >> 2;
    const int quad  = lane & 3;
    const int rA    = wid * 16 + group;

    float acc[16][4];
#pragma unroll
    for (int nt = 0; nt < 16; nt++)
#pragma unroll
        for (int j = 0; j < 4; j++) acc[nt][j] = 0.f;

#pragma unroll
    for (int kc = 0; kc < 8; kc++) {
        const int k0 = kc * 16 + quad * 2;
        const uint32_t ah0 = *reinterpret_cast<const uint32_t*>(&sAh[rA * GS + k0]);
        const uint32_t ah1 = *reinterpret_cast<const uint32_t*>(&sAh[(rA + 8) * GS + k0]);
        const uint32_t ah2 = *reinterpret_cast<const uint32_t*>(&sAh[rA * GS + k0 + 8]);
        const uint32_t ah3 = *reinterpret_cast<const uint32_t*>(&sAh[(rA + 8) * GS + k0 + 8]);
        const uint32_t al0 = *reinterpret_cast<const uint32_t*>(&sAl[rA * GS + k0]);
        const uint32_t al1 = *reinterpret_cast<const uint32_t*>(&sAl[(rA + 8) * GS + k0]);
        const uint32_t al2 = *reinterpret_cast<const uint32_t*>(&sAl[rA * GS + k0 + 8]);
        const uint32_t al3 = *reinterpret_cast<const uint32_t*>(&sAl[(rA + 8) * GS + k0 + 8]);
#pragma unroll
        for (int nt = 0; nt < 16; nt++) {
            const int n = nt * 8 + group;
            const uint32_t bh0 = *reinterpret_cast<const uint32_t*>(&sBh[n * GS + k0]);
            const uint32_t bh1 = *reinterpret_cast<const uint32_t*>(&sBh[n * GS + k0 + 8]);
            const uint32_t bl0 = *reinterpret_cast<const uint32_t*>(&sBl[n * GS + k0]);
            const uint32_t bl1 = *reinterpret_cast<const uint32_t*>(&sBl[n * GS + k0 + 8]);
            mma16816(acc[nt], ah0, ah1, ah2, ah3, bh0, bh1);
            mma16816(acc[nt], ah0, ah1, ah2, ah3, bl0, bl1);
            mma16816(acc[nt], al0, al1, al2, al3, bh0, bh1);
        }
    }

    const int r0 = row0 + rA;
    const int r1 = r0 + 8;
#pragma unroll
    for (int nt = 0; nt < 16; nt++) {
        const int c = nt * 8 + quad * 2;
        const float bx = __ldg(bias + c);
        const float by = __ldg(bias + c + 1);
        if (r0 < N_NODES) {
            __half2 h = __floats2half2_rn(acc[nt][0] + bx, acc[nt][1] + by);
            *reinterpret_cast<uint32_t*>(Wh + (size_t)r0 * D + c) =
                *reinterpret_cast<uint32_t*>(&h);
        }
        if (r1 < N_NODES) {
            __half2 h = __floats2half2_rn(acc[nt][2] + bx, acc[nt][3] + by);
            *reinterpret_cast<uint32_t*>(Wh + (size_t)r1 * D + c) =
                *reinterpret_cast<uint32_t*>(&h);
        }
    }
}

#define GEMM_SMEM (4 * 128 * GS * (int)sizeof(__half))

// ---------------------------------------------------------------------------
// Histogram (cnt arrives zeroed: module-load zero-init, then fill re-zeroes).
// ---------------------------------------------------------------------------
__global__ __launch_bounds__(256) void hist_kernel(
    const int* __restrict__ dst0, const int* __restrict__ dst1)
{
    const int e0 = (blockIdx.x * blockDim.x + threadIdx.x) * 4;
    if (e0 >= E_EDGES) return;
    const int* __restrict__ dst = blockIdx.y ? dst1 : dst0;
    int* __restrict__ cnt = blockIdx.y ? g_cnt1 : g_cnt0;
    const int4 d = __ldg(reinterpret_cast<const int4*>(dst + e0));
    atomicAdd(&cnt[d.x], 1);
    atomicAdd(&cnt[d.y], 1);
    atomicAdd(&cnt[d.z], 1);
    atomicAdd(&cnt[d.w], 1);
}

// ---------------------------------------------------------------------------
// Scan phase 1: per-block sums.
// ---------------------------------------------------------------------------
__global__ __launch_bounds__(SCAN_B) void scan_bsum_kernel() {
    const int rel = blockIdx.y;
    const int* __restrict__ cnt = rel ? g_cnt1 : g_cnt0;
    int* __restrict__ bsum = rel ? g_bsum1 : g_bsum0;

    const int i = blockIdx.x * SCAN_B + threadIdx.x;
    int x = (i < N_NODES) ? cnt[i] : 0;
#pragma unroll
    for (int o = 16; o; o >>= 1) x += __shfl_down_sync(0xffffffffu, x, o);

    __shared__ int ws[SCAN_B / 32];
    const int lane = threadIdx.x & 31, wid = threadIdx.x >> 5;
    if (lane == 0) ws[wid] = x;
    __syncthreads();
    if (wid == 0) {
        int t = (lane < SCAN_B / 32) ? ws[lane] : 0;
#pragma unroll
        for (int o = 16; o; o >>= 1) t += __shfl_down_sync(0xffffffffu, t, o);
        if (lane == 0) bsum[blockIdx.x] = t;
    }
}

// ---------------------------------------------------------------------------
// Scan phase 2 (final): per-block prefix by reducing bsum[0..bx), then local
// exclusive scan -> offs (segment starts).
// ---------------------------------------------------------------------------
__global__ __launch_bounds__(SCAN_B) void scan_final_kernel() {
    const int rel = blockIdx.y;
    const int* __restrict__ cnt  = rel ? g_cnt1  : g_cnt0;
    const int* __restrict__ bsum = rel ? g_bsum1 : g_bsum0;
    int* __restrict__ offs = rel ? g_offs1 : g_offs0;

    const int lane = threadIdx.x & 31, wid = threadIdx.x >> 5;

    // --- block prefix: sum of bsum[0 .. blockIdx.x) ---
    __shared__ int sred[SCAN_B / 32];
    int v = (threadIdx.x < blockIdx.x) ? bsum[threadIdx.x] : 0;   // blockIdx.x <= 97 < SCAN_B
#pragma unroll
    for (int o = 16; o; o >>= 1) v += __shfl_down_sync(0xffffffffu, v, o);
    if (lane == 0) sred[wid] = v;
    __syncthreads();
    if (threadIdx.x == 0) {
        int t = 0;
#pragma unroll
        for (int w = 0; w < SCAN_B / 32; w++) t += sred[w];
        sred[0] = t;
    }
    __syncthreads();
    const int base = sred[0];
    __syncthreads();

    // --- local exclusive scan ---
    const int i = blockIdx.x * SCAN_B + threadIdx.x;
    const int x = (i < N_NODES) ? cnt[i] : 0;
    int s = x;
#pragma unroll
    for (int o = 1; o < 32; o <<= 1) {
        int t = __shfl_up_sync(0xffffffffu, s, o);
        if (lane >= o) s += t;
    }
    __shared__ int ws[SCAN_B / 32];
    if (lane == 31) ws[wid] = s;
    __syncthreads();
    if (wid == 0) {
        int t = (lane < SCAN_B / 32) ? ws[lane] : 0;
#pragma unroll
        for (int o = 1; o < 32; o <<= 1) {
            int u = __shfl_up_sync(0xffffffffu, t, o);
            if (lane >= o) t += u;
        }
        if (lane < SCAN_B / 32) ws[lane] = t;
    }
    __syncthreads();
    const int prefix = (wid > 0) ? ws[wid - 1] : 0;
    if (i < N_NODES) offs[i] = base + prefix + s - x;
}

// ---------------------------------------------------------------------------
// Fill: atomicAdd directly on offs (post-fill offs[n] = segment end).
// Also re-zeroes cnt for the next call.
// ---------------------------------------------------------------------------
__global__ __launch_bounds__(256) void fill_kernel(
    const int* __restrict__ src0, const int* __restrict__ dst0,
    const int* __restrict__ src1, const int* __restrict__ dst1)
{
    const int gt = blockIdx.x * blockDim.x + threadIdx.x;
    int* __restrict__ cnt = blockIdx.y ? g_cnt1 : g_cnt0;
    if (gt < N_NODES) cnt[gt] = 0;

    const int e0 = gt * 4;
    if (e0 >= E_EDGES) return;
    const int* __restrict__ src = blockIdx.y ? src1 : src0;
    const int* __restrict__ dst = blockIdx.y ? dst1 : dst0;
    int* __restrict__ offs = blockIdx.y ? g_offs1 : g_offs0;
    int* __restrict__ srt  = blockIdx.y ? g_srt1  : g_srt0;

    const int4 d = __ldg(reinterpret_cast<const int4*>(dst + e0));
    const int4 s = __ldg(reinterpret_cast<const int4*>(src + e0));
    const int p0 = atomicAdd(&offs[d.x], 1);
    const int p1 = atomicAdd(&offs[d.y], 1);
    const int p2 = atomicAdd(&offs[d.z], 1);
    const int p3 = atomicAdd(&offs[d.w], 1);
    srt[p0] = s.x; srt[p1] = s.y; srt[p2] = s.z; srt[p3] = s.w;
}

// ---------------------------------------------------------------------------
// Gather v3: warp per node; indices preloaded into registers (coalesced) and
// distributed via shfl; half-warp per row (uint4 = full fp16 row per 16 lanes)
// so two edges are in flight per instruction; rel0/rel1 interleaved.
// ---------------------------------------------------------------------------
__device__ __forceinline__ void accum8(float* a, uint4 v) {
    const __half2* h = reinterpret_cast<const __half2*>(&v);
#pragma unroll
    for (int i = 0; i < 4; i++) {
        const float2 f = __half22float2(h[i]);
        a[2 * i]     += f.x;
        a[2 * i + 1] += f.y;
    }
}

__global__ __launch_bounds__(256) void gather_kernel(float* __restrict__ out) {
    const int n = blockIdx.x * 8 + (threadIdx.x >> 5);
    if (n >= N_NODES) return;
    const int lane = threadIdx.x & 31;
    const int half = lane >> 4;
    const int l16  = lane & 15;

    const int end0 = __ldg(g_offs0 + n);
    const int beg0 = n ? __ldg(g_offs0 + n - 1) : 0;
    const int end1 = __ldg(g_offs1 + n);
    const int beg1 = n ? __ldg(g_offs1 + n - 1) : 0;
    const int d0 = end0 - beg0, d1 = end1 - beg1;

    // Preload up to 32 indices per relation, coalesced.
    const int i0 = (lane < d0) ? __ldg(g_srt0 + beg0 + lane) : 0;
    const int i1 = (lane < d1) ? __ldg(g_srt1 + beg1 + lane) : 0;

    float acc0[8] = {0.f, 0.f, 0.f, 0.f, 0.f, 0.f, 0.f, 0.f};
    float acc1[8] = {0.f, 0.f, 0.f, 0.f, 0.f, 0.f, 0.f, 0.f};

    const int m0 = min(d0, 32), m1 = min(d1, 32);
    const int T = (max(m0, m1) + 1) >> 1;
#pragma unroll 4
    for (int t = 0; t < T; t++) {
        const int j = 2 * t + half;
        const int s0 = __shfl_sync(0xffffffffu, i0, j & 31);
        const int s1 = __shfl_sync(0xffffffffu, i1, j & 31);
        if (j < m0) {
            const uint4 v = __ldg(
                reinterpret_cast<const uint4*>(g_Wh0 + (size_t)s0 * D) + l16);
            accum8(acc0, v);
        }
        if (j < m1) {
            const uint4 v = __ldg(
                reinterpret_cast<const uint4*>(g_Wh1 + (size_t)s1 * D) + l16);
            accum8(acc1, v);
        }
    }
    // Rare tails (degree > 32): each half-warp takes alternating edges.
    for (int e = beg0 + 32 + half; e < end0; e += 2) {
        const int s = __ldg(g_srt0 + e);
        const uint4 v = __ldg(
            reinterpret_cast<const uint4*>(g_Wh0 + (size_t)s * D) + l16);
        accum8(acc0, v);
    }
    for (int e = beg1 + 32 + half; e < end1; e += 2) {
        const int s = __ldg(g_srt1 + e);
        const uint4 v = __ldg(
            reinterpret_cast<const uint4*>(g_Wh1 + (size_t)s * D) + l16);
        accum8(acc1, v);
    }

    // Combine the two half-warps (same columns, different edge subsets).
#pragma unroll
    for (int q = 0; q < 8; q++) {
        acc0[q] += __shfl_xor_sync(0xffffffffu, acc0[q], 16);
        acc1[q] += __shfl_xor_sync(0xffffffffu, acc1[q], 16);
    }

    const float inv0 = 1.0f / fmaxf((float)d0, 1.0f);
    const float inv1 = 1.0f / fmaxf((float)d1, 1.0f);

    float4 w;
    const int qb = half * 4;
    w.x = acc0[qb + 0] * inv0 + acc1[qb + 0] * inv1;
    w.y = acc0[qb + 1] * inv0 + acc1[qb + 1] * inv1;
    w.z = acc0[qb + 2] * inv0 + acc1[qb + 2] * inv1;
    w.w = acc0[qb + 3] * inv0 + acc1[qb + 3] * inv1;
    *reinterpret_cast<float4*>(out + (size_t)n * D + l16 * 8 + half * 4) = w;
}

// ---------------------------------------------------------------------------
// inputs: feat, W0, b0, W1, b1, src0, dst0, src1, dst1
// ---------------------------------------------------------------------------
extern "C" void kernel_launch(void* const* d_in, const int* in_sizes, int n_in,
                              void* d_out, int out_size) {
    const float* feat = (const float*)d_in[0];
    const float* W0   = (const float*)d_in[1];
    const float* b0   = (const float*)d_in[2];
    const float* W1   = (const float*)d_in[3];
    const float* b1   = (const float*)d_in[4];
    const int*   src0 = (const int*)d_in[5];
    const int*   dst0 = (const int*)d_in[6];
    const int*   src1 = (const int*)d_in[7];
    const int*   dst1 = (const int*)d_in[8];
    float* out = (float*)d_out;

    cudaFuncSetAttribute(mma_gemm_kernel,
                         cudaFuncAttributeMaxDynamicSharedMemorySize, GEMM_SMEM);

    // Fork: HMMA GEMM concurrent with the CSR build.
    cudaEventRecord(g_ss.fork, 0);
    cudaStreamWaitEvent(g_ss.s, g_ss.fork, 0);
    dim3 ggrid(GTILES, 2);
    mma_gemm_kernel<<<ggrid, 256, GEMM_SMEM, g_ss.s>>>(feat, W0, b0, W1, b1);
    cudaEventRecord(g_ss.join, g_ss.s);

    // Main stream: CSR build (cnt already zeroed by previous call / load-init).
    dim3 egrid4((E_EDGES / 4 + 255) / 256, 2);
    hist_kernel<<<egrid4, 256>>>(dst0, dst1);

    dim3 sgrid(NBLK, 2);
    scan_bsum_kernel<<<sgrid, SCAN_B>>>();
    scan_final_kernel<<<sgrid, SCAN_B>>>();

    fill_kernel<<<egrid4, 256>>>(src0, dst0, src1, dst1);

    // Join, then gather.
    cudaStreamWaitEvent(0, g_ss.join, 0);
    gather_kernel<<<(N_NODES + 7) / 8, 256>>>(out);
}

// round 8
// speedup vs baseline: 1.2201x; 1.2201x over previous
#include <cuda_runtime.h>
#include <cuda_fp16.h>
#include <stdint.h>

#define N_NODES 50000
#define E_EDGES 800000
#define D 128
#define SCAN_B 512
#define NBLK ((N_NODES + SCAN_B - 1) / SCAN_B)   // 98
#define GTILES ((N_NODES + 127) / 128)           // 391
#define GS 136                                    // smem f16 stride (bank-safe)

// ---------------------------------------------------------------------------
// Scratch (__device__ globals; zero-initialized at module load; no allocs).
// ---------------------------------------------------------------------------
__device__ __half g_Wh0[(size_t)N_NODES * D];
__device__ __half g_Wh1[(size_t)N_NODES * D];
__device__ int   g_cnt0[N_NODES];     // re-zeroed by fill_kernel each call
__device__ int   g_cnt1[N_NODES];
__device__ int   g_offs0[N_NODES];    // scan writes starts; fill bumps to ends
__device__ int   g_offs1[N_NODES];
__device__ int   g_srt0[E_EDGES];
__device__ int   g_srt1[E_EDGES];
__device__ int   g_bsum0[NBLK];
__device__ int   g_bsum1[NBLK];

// ---------------------------------------------------------------------------
// Host-side stream/event resources (created once; host-only resources).
// ---------------------------------------------------------------------------
struct SideStream {
    cudaStream_t s;
    cudaEvent_t  fork, join;
    SideStream() {
        cudaStreamCreateWithFlags(&s, cudaStreamNonBlocking);
        cudaEventCreateWithFlags(&fork, cudaEventDisableTiming);
        cudaEventCreateWithFlags(&join, cudaEventDisableTiming);
    }
};
static SideStream g_ss;

// ---------------------------------------------------------------------------
// Warp-level HMMA m16n8k16 (sm_80+ baseline PTX).
// ---------------------------------------------------------------------------
__device__ __forceinline__ void mma16816(float* d,
                                         uint32_t a0, uint32_t a1,
                                         uint32_t a2, uint32_t a3,
                                         uint32_t b0, uint32_t b1) {
    asm volatile(
        "mma.sync.aligned.m16n8k16.row.col.f32.f16.f16.f32 "
        "{%0,%1,%2,%3}, {%4,%5,%6,%7}, {%8,%9}, {%0,%1,%2,%3};"
        : "+f"(d[0]), "+f"(d[1]), "+f"(d[2]), "+f"(d[3])
        : "r"(a0), "r"(a1), "r"(a2), "r"(a3), "r"(b0), "r"(b1));
}

// ---------------------------------------------------------------------------
// HMMA GEMM: Wh = fp16(feat @ W + b), Markidis hi/lo split. Side stream.
// ---------------------------------------------------------------------------
__global__ __launch_bounds__(256, 1) void mma_gemm_kernel(
    const float* __restrict__ feat,
    const float* __restrict__ W0, const float* __restrict__ b0,
    const float* __restrict__ W1, const float* __restrict__ b1)
{
    extern __shared__ __align__(16) char smem[];
    __half* sAh = reinterpret_cast<__half*>(smem);
    __half* sAl = sAh + 128 * GS;
    __half* sBh = sAl + 128 * GS;
    __half* sBl = sBh + 128 * GS;

    const int rel = blockIdx.y;
    const float* __restrict__ W    = rel ? W1 : W0;
    const float* __restrict__ bias = rel ? b1 : b0;
    __half* __restrict__ Wh = rel ? g_Wh1 : g_Wh0;

    const int tid  = threadIdx.x;
    const int row0 = blockIdx.x * 128;

    for (int i = tid; i < D * D; i += 256) {
        const int k = i >> 7, n = i & 127;
        const float w = __ldg(W + i);
        const __half h = __float2half_rn(w);
        const __half l = __float2half_rn(w - __half2float(h));
        sBh[n * GS + k] = h;
        sBl[n * GS + k] = l;
    }
    for (int i = tid; i < 128 * D; i += 256) {
        const int r = i >> 7, k = i & 127;
        const int gr = row0 + r;
        const float a = (gr < N_NODES) ? __ldg(feat + (size_t)gr * D + k) : 0.f;
        const __half h = __float2half_rn(a);
        const __half l = __float2half_rn(a - __half2float(h));
        sAh[r * GS + k] = h;
        sAl[r * GS + k] = l;
    }
    __syncthreads();

    const int wid   = tid >> 5;
    const int lane  = tid & 31;
    const int group = lane >> 2;
    const int quad  = lane & 3;
    const int rA    = wid * 16 + group;

    float acc[16][4];
#pragma unroll
    for (int nt = 0; nt < 16; nt++)
#pragma unroll
        for (int j = 0; j < 4; j++) acc[nt][j] = 0.f;

#pragma unroll
    for (int kc = 0; kc < 8; kc++) {
        const int k0 = kc * 16 + quad * 2;
        const uint32_t ah0 = *reinterpret_cast<const uint32_t*>(&sAh[rA * GS + k0]);
        const uint32_t ah1 = *reinterpret_cast<const uint32_t*>(&sAh[(rA + 8) * GS + k0]);
        const uint32_t ah2 = *reinterpret_cast<const uint32_t*>(&sAh[rA * GS + k0 + 8]);
        const uint32_t ah3 = *reinterpret_cast<const uint32_t*>(&sAh[(rA + 8) * GS + k0 + 8]);
        const uint32_t al0 = *reinterpret_cast<const uint32_t*>(&sAl[rA * GS + k0]);
        const uint32_t al1 = *reinterpret_cast<const uint32_t*>(&sAl[(rA + 8) * GS + k0]);
        const uint32_t al2 = *reinterpret_cast<const uint32_t*>(&sAl[rA * GS + k0 + 8]);
        const uint32_t al3 = *reinterpret_cast<const uint32_t*>(&sAl[(rA + 8) * GS + k0 + 8]);
#pragma unroll
        for (int nt = 0; nt < 16; nt++) {
            const int n = nt * 8 + group;
            const uint32_t bh0 = *reinterpret_cast<const uint32_t*>(&sBh[n * GS + k0]);
            const uint32_t bh1 = *reinterpret_cast<const uint32_t*>(&sBh[n * GS + k0 + 8]);
            const uint32_t bl0 = *reinterpret_cast<const uint32_t*>(&sBl[n * GS + k0]);
            const uint32_t bl1 = *reinterpret_cast<const uint32_t*>(&sBl[n * GS + k0 + 8]);
            mma16816(acc[nt], ah0, ah1, ah2, ah3, bh0, bh1);
            mma16816(acc[nt], ah0, ah1, ah2, ah3, bl0, bl1);
            mma16816(acc[nt], al0, al1, al2, al3, bh0, bh1);
        }
    }

    const int r0 = row0 + rA;
    const int r1 = r0 + 8;
#pragma unroll
    for (int nt = 0; nt < 16; nt++) {
        const int c = nt * 8 + quad * 2;
        const float bx = __ldg(bias + c);
        const float by = __ldg(bias + c + 1);
        if (r0 < N_NODES) {
            __half2 h = __floats2half2_rn(acc[nt][0] + bx, acc[nt][1] + by);
            *reinterpret_cast<uint32_t*>(Wh + (size_t)r0 * D + c) =
                *reinterpret_cast<uint32_t*>(&h);
        }
        if (r1 < N_NODES) {
            __half2 h = __floats2half2_rn(acc[nt][2] + bx, acc[nt][3] + by);
            *reinterpret_cast<uint32_t*>(Wh + (size_t)r1 * D + c) =
                *reinterpret_cast<uint32_t*>(&h);
        }
    }
}

#define GEMM_SMEM (4 * 128 * GS * (int)sizeof(__half))

// ---------------------------------------------------------------------------
// Histogram (cnt arrives zeroed: module-load zero-init, then fill re-zeroes).
// ---------------------------------------------------------------------------
__global__ __launch_bounds__(256) void hist_kernel(
    const int* __restrict__ dst0, const int* __restrict__ dst1)
{
    const int e0 = (blockIdx.x * blockDim.x + threadIdx.x) * 4;
    if (e0 >= E_EDGES) return;
    const int* __restrict__ dst = blockIdx.y ? dst1 : dst0;
    int* __restrict__ cnt = blockIdx.y ? g_cnt1 : g_cnt0;
    const int4 d = __ldg(reinterpret_cast<const int4*>(dst + e0));
    atomicAdd(&cnt[d.x], 1);
    atomicAdd(&cnt[d.y], 1);
    atomicAdd(&cnt[d.z], 1);
    atomicAdd(&cnt[d.w], 1);
}

// ---------------------------------------------------------------------------
// Scan phase 1: per-block sums.
// ---------------------------------------------------------------------------
__global__ __launch_bounds__(SCAN_B) void scan_bsum_kernel() {
    const int rel = blockIdx.y;
    const int* __restrict__ cnt = rel ? g_cnt1 : g_cnt0;
    int* __restrict__ bsum = rel ? g_bsum1 : g_bsum0;

    const int i = blockIdx.x * SCAN_B + threadIdx.x;
    int x = (i < N_NODES) ? cnt[i] : 0;
#pragma unroll
    for (int o = 16; o; o >>= 1) x += __shfl_down_sync(0xffffffffu, x, o);

    __shared__ int ws[SCAN_B / 32];
    const int lane = threadIdx.x & 31, wid = threadIdx.x >> 5;
    if (lane == 0) ws[wid] = x;
    __syncthreads();
    if (wid == 0) {
        int t = (lane < SCAN_B / 32) ? ws[lane] : 0;
#pragma unroll
        for (int o = 16; o; o >>= 1) t += __shfl_down_sync(0xffffffffu, t, o);
        if (lane == 0) bsum[blockIdx.x] = t;
    }
}

// ---------------------------------------------------------------------------
// Scan phase 2 (final): per-block prefix by reducing bsum[0..bx), then local
// exclusive scan -> offs (segment starts).
// ---------------------------------------------------------------------------
__global__ __launch_bounds__(SCAN_B) void scan_final_kernel() {
    const int rel = blockIdx.y;
    const int* __restrict__ cnt  = rel ? g_cnt1  : g_cnt0;
    const int* __restrict__ bsum = rel ? g_bsum1 : g_bsum0;
    int* __restrict__ offs = rel ? g_offs1 : g_offs0;

    const int lane = threadIdx.x & 31, wid = threadIdx.x >> 5;

    __shared__ int sred[SCAN_B / 32];
    int v = (threadIdx.x < blockIdx.x) ? bsum[threadIdx.x] : 0;
#pragma unroll
    for (int o = 16; o; o >>= 1) v += __shfl_down_sync(0xffffffffu, v, o);
    if (lane == 0) sred[wid] = v;
    __syncthreads();
    if (threadIdx.x == 0) {
        int t = 0;
#pragma unroll
        for (int w = 0; w < SCAN_B / 32; w++) t += sred[w];
        sred[0] = t;
    }
    __syncthreads();
    const int base = sred[0];
    __syncthreads();

    const int i = blockIdx.x * SCAN_B + threadIdx.x;
    const int x = (i < N_NODES) ? cnt[i] : 0;
    int s = x;
#pragma unroll
    for (int o = 1; o < 32; o <<= 1) {
        int t = __shfl_up_sync(0xffffffffu, s, o);
        if (lane >= o) s += t;
    }
    __shared__ int ws[SCAN_B / 32];
    if (lane == 31) ws[wid] = s;
    __syncthreads();
    if (wid == 0) {
        int t = (lane < SCAN_B / 32) ? ws[lane] : 0;
#pragma unroll
        for (int o = 1; o < 32; o <<= 1) {
            int u = __shfl_up_sync(0xffffffffu, t, o);
            if (lane >= o) t += u;
        }
        if (lane < SCAN_B / 32) ws[lane] = t;
    }
    __syncthreads();
    const int prefix = (wid > 0) ? ws[wid - 1] : 0;
    if (i < N_NODES) offs[i] = base + prefix + s - x;
}

// ---------------------------------------------------------------------------
// Fill: atomicAdd directly on offs (post-fill offs[n] = segment end).
// Also re-zeroes cnt for the next call.
// ---------------------------------------------------------------------------
__global__ __launch_bounds__(256) void fill_kernel(
    const int* __restrict__ src0, const int* __restrict__ dst0,
    const int* __restrict__ src1, const int* __restrict__ dst1)
{
    const int gt = blockIdx.x * blockDim.x + threadIdx.x;
    int* __restrict__ cnt = blockIdx.y ? g_cnt1 : g_cnt0;
    if (gt < N_NODES) cnt[gt] = 0;

    const int e0 = gt * 4;
    if (e0 >= E_EDGES) return;
    const int* __restrict__ src = blockIdx.y ? src1 : src0;
    const int* __restrict__ dst = blockIdx.y ? dst1 : dst0;
    int* __restrict__ offs = blockIdx.y ? g_offs1 : g_offs0;
    int* __restrict__ srt  = blockIdx.y ? g_srt1  : g_srt0;

    const int4 d = __ldg(reinterpret_cast<const int4*>(dst + e0));
    const int4 s = __ldg(reinterpret_cast<const int4*>(src + e0));
    const int p0 = atomicAdd(&offs[d.x], 1);
    const int p1 = atomicAdd(&offs[d.y], 1);
    const int p2 = atomicAdd(&offs[d.z], 1);
    const int p3 = atomicAdd(&offs[d.w], 1);
    srt[p0] = s.x; srt[p1] = s.y; srt[p2] = s.z; srt[p3] = s.w;
}

// ---------------------------------------------------------------------------
// Warp-per-node pull gather over fp16 Wh (R6 shape, unroll widened to 8).
// ---------------------------------------------------------------------------
__device__ __forceinline__ void acc_u2(float4& a, uint2 u) {
    const __half2 h0 = *reinterpret_cast<__half2*>(&u.x);
    const __half2 h1 = *reinterpret_cast<__half2*>(&u.y);
    const float2 f0 = __half22float2(h0);
    const float2 f1 = __half22float2(h1);
    a.x += f0.x; a.y += f0.y; a.z += f1.x; a.w += f1.y;
}
__device__ __forceinline__ uint2 ld_row_h(const __half* __restrict__ Wh,
                                          int s, int lane) {
    return __ldg(reinterpret_cast<const uint2*>(Wh + (size_t)s * D) + lane);
}
__device__ __forceinline__ float4 gather_rel(
    const __half* __restrict__ Wh, const int* __restrict__ srt,
    int beg, int end, int lane)
{
    float4 acc = make_float4(0.f, 0.f, 0.f, 0.f);
    int e = beg;
    for (; e + 8 <= end; e += 8) {
        int s[8];
#pragma unroll
        for (int j = 0; j < 8; j++) s[j] = __ldg(srt + e + j);
        uint2 u[8];
#pragma unroll
        for (int j = 0; j < 8; j++) u[j] = ld_row_h(Wh, s[j], lane);
#pragma unroll
        for (int j = 0; j < 8; j++) acc_u2(acc, u[j]);
    }
    if (e + 4 <= end) {
        int s[4];
#pragma unroll
        for (int j = 0; j < 4; j++) s[j] = __ldg(srt + e + j);
        uint2 u[4];
#pragma unroll
        for (int j = 0; j < 4; j++) u[j] = ld_row_h(Wh, s[j], lane);
#pragma unroll
        for (int j = 0; j < 4; j++) acc_u2(acc, u[j]);
        e += 4;
    }
    for (; e < end; e++)
        acc_u2(acc, ld_row_h(Wh, __ldg(srt + e), lane));
    return acc;
}

__global__ __launch_bounds__(256) void gather_kernel(float* __restrict__ out) {
    const int n = blockIdx.x * 8 + (threadIdx.x >> 5);
    if (n >= N_NODES) return;
    const int lane = threadIdx.x & 31;

    const int end0 = __ldg(g_offs0 + n);
    const int beg0 = n ? __ldg(g_offs0 + n - 1) : 0;
    const int end1 = __ldg(g_offs1 + n);
    const int beg1 = n ? __ldg(g_offs1 + n - 1) : 0;

    const float4 a0 = gather_rel(g_Wh0, g_srt0, beg0, end0, lane);
    const float4 a1 = gather_rel(g_Wh1, g_srt1, beg1, end1, lane);

    const float inv0 = 1.0f / fmaxf((float)(end0 - beg0), 1.0f);
    const float inv1 = 1.0f / fmaxf((float)(end1 - beg1), 1.0f);

    float4 r;
    r.x = a0.x * inv0 + a1.x * inv1;
    r.y = a0.y * inv0 + a1.y * inv1;
    r.z = a0.z * inv0 + a1.z * inv1;
    r.w = a0.w * inv0 + a1.w * inv1;
    reinterpret_cast<float4*>(out + (size_t)n * D)[lane] = r;
}

// ---------------------------------------------------------------------------
// inputs: feat, W0, b0, W1, b1, src0, dst0, src1, dst1
// ---------------------------------------------------------------------------
extern "C" void kernel_launch(void* const* d_in, const int* in_sizes, int n_in,
                              void* d_out, int out_size) {
    const float* feat = (const float*)d_in[0];
    const float* W0   = (const float*)d_in[1];
    const float* b0   = (const float*)d_in[2];
    const float* W1   = (const float*)d_in[3];
    const float* b1   = (const float*)d_in[4];
    const int*   src0 = (const int*)d_in[5];
    const int*   dst0 = (const int*)d_in[6];
    const int*   src1 = (const int*)d_in[7];
    const int*   dst1 = (const int*)d_in[8];
    float* out = (float*)d_out;

    cudaFuncSetAttribute(mma_gemm_kernel,
                         cudaFuncAttributeMaxDynamicSharedMemorySize, GEMM_SMEM);

    // Fork: HMMA GEMM concurrent with the CSR build.
    cudaEventRecord(g_ss.fork, 0);
    cudaStreamWaitEvent(g_ss.s, g_ss.fork, 0);
    dim3 ggrid(GTILES, 2);
    mma_gemm_kernel<<<ggrid, 256, GEMM_SMEM, g_ss.s>>>(feat, W0, b0, W1, b1);
    cudaEventRecord(g_ss.join, g_ss.s);

    // Main stream: CSR build (cnt already zeroed by previous call / load-init).
    dim3 egrid4((E_EDGES / 4 + 255) / 256, 2);
    hist_kernel<<<egrid4, 256>>>(dst0, dst1);

    dim3 sgrid(NBLK, 2);
    scan_bsum_kernel<<<sgrid, SCAN_B>>>();
    scan_final_kernel<<<sgrid, SCAN_B>>>();

    fill_kernel<<<egrid4, 256>>>(src0, dst0, src1, dst1);

    // Join, then gather.
    cudaStreamWaitEvent(0, g_ss.join, 0);
    gather_kernel<<<(N_NODES + 7) / 8, 256>>>(out);
}